// round 11
// baseline (speedup 1.0000x reference)
#include <cuda_runtime.h>
#include <cuda_fp16.h>
#include <cstdint>

// Problem dims
#define B_  32
#define S_  2048
#define E_  256
#define H_  256
#define M_  (B_ * S_)   // 65536
#define N_  (3 * H_)    // 768
#define K_  (2 * E_)    // 512

#define CHUNKS 64
#define CHLEN  (S_ / CHUNKS)   // 32
#define CHAINS (B_ * H_)       // 8192
#define NBLK   (B_ * CHUNKS)   // 2048 scan blocks

// Scratch (static device arrays; no allocation)
__device__ __half g_gates[(size_t)M_ * N_];   // activated z|f|o  [M,768] fp16
__device__ __half g_x16[(size_t)M_ * E_];     // x in fp16
__device__ __half g_Wt16[(size_t)N_ * K_];    // W transposed fp16 [768,512]
__device__ float  g_locA[NBLK * H_];          // per-block local A (prod f)
__device__ float  g_locB[NBLK * H_];          // per-block local B
__device__ float  g_incl[NBLK * H_];          // per-block inclusive c
__device__ int    g_flag[NBLK];               // 0=none, 1=local, 2=inclusive

__device__ __forceinline__ float sigm(float x)      { return 1.0f / (1.0f + __expf(-x)); }
__device__ __forceinline__ float tanh_fast(float x) { return 2.0f / (1.0f + __expf(-2.0f * x)) - 1.0f; }

__device__ __forceinline__ uint32_t smem_u32(const void* p) {
    uint32_t a;
    asm("{ .reg .u64 t; cvta.to.shared.u64 t, %1; cvt.u32.u64 %0, t; }" : "=r"(a) : "l"(p));
    return a;
}

#define LDSM_X4(r0, r1, r2, r3, a)                                              \
    asm volatile("ldmatrix.sync.aligned.m8n8.x4.shared.b16 {%0,%1,%2,%3}, [%4];"\
                 : "=r"(r0), "=r"(r1), "=r"(r2), "=r"(r3) : "r"(a))

#define MMA_F16(c, a0, a1, a2, a3, b0, b1)                                      \
    asm volatile("mma.sync.aligned.m16n8k16.row.col.f32.f16.f16.f32 "           \
                 "{%0,%1,%2,%3}, {%4,%5,%6,%7}, {%8,%9}, {%0,%1,%2,%3};"        \
                 : "+f"((c)[0]), "+f"((c)[1]), "+f"((c)[2]), "+f"((c)[3])       \
                 : "r"(a0), "r"(a1), "r"(a2), "r"(a3), "r"(b0), "r"(b1))

__device__ __forceinline__ void cp16(uint32_t dst, const void* src, int sz) {
    asm volatile("cp.async.cg.shared.global [%0], [%1], 16, %2;" :: "r"(dst), "l"(src), "r"(sz));
}
#define CP_COMMIT() asm volatile("cp.async.commit_group;" ::: "memory")
#define CP_WAIT2()  asm volatile("cp.async.wait_group 2;" ::: "memory")

// ---------------------------------------------------------------------------
// flag init (graph-replay safe reset)
// ---------------------------------------------------------------------------
__global__ __launch_bounds__(256)
void flag_init()
{
    g_flag[blockIdx.x * 256 + threadIdx.x] = 0;
}

// ---------------------------------------------------------------------------
// x fp32 -> fp16
// ---------------------------------------------------------------------------
__global__ __launch_bounds__(256)
void convert_x(const float* __restrict__ x)
{
    long i = (long)blockIdx.x * 256 + threadIdx.x;     // one float4 pair each
    const float4* src = (const float4*)x;
    float4 v0 = src[2 * i], v1 = src[2 * i + 1];
    __half2 h0 = __floats2half2_rn(v0.x, v0.y);
    __half2 h1 = __floats2half2_rn(v0.z, v0.w);
    __half2 h2 = __floats2half2_rn(v1.x, v1.y);
    __half2 h3 = __floats2half2_rn(v1.z, v1.w);
    uint4 o;
    o.x = *(uint32_t*)&h0; o.y = *(uint32_t*)&h1;
    o.z = *(uint32_t*)&h2; o.w = *(uint32_t*)&h3;
    *((uint4*)g_x16 + i) = o;
}

// ---------------------------------------------------------------------------
// W [512,768] fp32 -> Wt16 [768,512] fp16 (transposed)
// ---------------------------------------------------------------------------
__global__ void prep_w(const float* __restrict__ W)
{
    __shared__ float t[32][33];
    int n = blockIdx.x * 32 + threadIdx.x;
    int k = blockIdx.y * 32 + threadIdx.y;
#pragma unroll
    for (int j = 0; j < 32; j += 8)
        t[threadIdx.y + j][threadIdx.x] = W[(long)(k + j) * N_ + n];
    __syncthreads();
    int n2 = blockIdx.x * 32 + threadIdx.y;
    int k2 = blockIdx.y * 32 + threadIdx.x;
#pragma unroll
    for (int j = 0; j < 32; j += 8)
        g_Wt16[(long)(n2 + j) * K_ + k2] = __float2half_rn(t[threadIdx.x][threadIdx.y + j]);
}

// ---------------------------------------------------------------------------
// GEMM (R8/R10 config — best measured): gates = [x_t, x_{t-1}] @ W + b.
// fp16 mma.sync m16n8k16, fp32 accum. CTA tile 128x128, BK=64 (8 phases),
// 8 warps (2x4), warp tile 64x32, 3-stage cp.async, 256 thr, 2 CTAs/SM.
// smem row stride 72 halves (144B): conflict-free ldmatrix.
// B stored [n][k] k-contiguous -> NON-trans ldmatrix = col-major B fragment.
// ---------------------------------------------------------------------------
#define RS        72                      // halves per smem row
#define A_BYTES   (128 * RS * 2)          // 18432
#define STAGE_SZ  (2 * A_BYTES)           // A + B = 36864
#define STAGES    3
#define SMEM_BYTES (STAGES * STAGE_SZ)    // 110592 (2 CTAs = 216 KB <= 228 KB)

__global__ __launch_bounds__(256, 2)
void gates_gemm(const float* __restrict__ bias)
{
    extern __shared__ char smem[];
    const uint32_t sb = smem_u32(smem);
    const int tid  = threadIdx.x;
    const int lane = tid & 31;
    const int wid  = tid >> 5;
    const int warp_m = wid & 1;
    const int warp_n = wid >> 1;
    const int m0 = blockIdx.y * 128;
    const int n0 = blockIdx.x * 128;

    auto stageA = [&](int s) -> uint32_t { return sb + s * STAGE_SZ; };
    auto stageB = [&](int s) -> uint32_t { return sb + s * STAGE_SZ + A_BYTES; };

    float acc[4][4][4];
#pragma unroll
    for (int a = 0; a < 4; a++)
#pragma unroll
        for (int b = 0; b < 4; b++)
#pragma unroll
            for (int c = 0; c < 4; c++) acc[a][b][c] = 0.0f;

    auto load_tile = [&](int kt, int s) {
        const int k0 = kt * 64;
        const uint32_t ab = stageA(s), bb = stageB(s);
#pragma unroll
        for (int i = 0; i < 4; i++) {
            int idx = tid + i * 256;
            int r = idx >> 3, ci = idx & 7;          // row 0..127, 16B chunk 0..7
            uint32_t dst = ab + r * (RS * 2) + ci * 16;
            int m = m0 + r;
            const __half* src;
            int sz = 16;
            if (k0 < 256) {
                src = g_x16 + (long)m * E_ + k0 + ci * 8;
            } else if ((m & (S_ - 1)) == 0) {
                src = g_x16; sz = 0;                  // t==0: zero fill
            } else {
                src = g_x16 + (long)(m - 1) * E_ + (k0 - 256) + ci * 8;
            }
            cp16(dst, src, sz);
        }
#pragma unroll
        for (int i = 0; i < 4; i++) {
            int idx = tid + i * 256;
            int r = idx >> 3, ci = idx & 7;
            uint32_t dst = bb + r * (RS * 2) + ci * 16;
            cp16(dst, g_Wt16 + (long)(n0 + r) * K_ + k0 + ci * 8, 16);
        }
    };

    load_tile(0, 0); CP_COMMIT();
    load_tile(1, 1); CP_COMMIT();
    load_tile(2, 2); CP_COMMIT();

    for (int kt = 0; kt < 8; kt++) {
        const int s = kt % STAGES;
        CP_WAIT2();
        __syncthreads();

        const uint32_t ab = stageA(s), bb = stageB(s);
#pragma unroll
        for (int ks = 0; ks < 4; ks++) {
            const int kk = ks * 16;
            uint32_t af[4][4], bf[4][2];
#pragma unroll
            for (int mt = 0; mt < 4; mt++) {
                int mBase = warp_m * 64 + mt * 16;
                int mi = lane >> 3;
                int row = mBase + ((mi & 1) << 3) + (lane & 7);
                int col = kk + ((mi >> 1) << 3);
                uint32_t a = ab + (row * RS + col) * 2;
                LDSM_X4(af[mt][0], af[mt][1], af[mt][2], af[mt][3], a);
            }
#pragma unroll
            for (int p = 0; p < 2; p++) {
                int nBase = warp_n * 32 + p * 16;
                int mi = lane >> 3;
                int row = nBase + ((mi >> 1) << 3) + (lane & 7);
                int col = kk + ((mi & 1) << 3);
                uint32_t a = bb + (row * RS + col) * 2;
                LDSM_X4(bf[2 * p][0], bf[2 * p][1], bf[2 * p + 1][0], bf[2 * p + 1][1], a);
            }
#pragma unroll
            for (int mt = 0; mt < 4; mt++)
#pragma unroll
                for (int nt = 0; nt < 4; nt++)
                    MMA_F16(acc[mt][nt], af[mt][0], af[mt][1], af[mt][2], af[mt][3],
                            bf[nt][0], bf[nt][1]);
        }
        __syncthreads();
        if (kt + STAGES < 8) load_tile(kt + STAGES, s);
        CP_COMMIT();    // always commit (possibly empty) to keep wait_group math
    }

    // Epilogue: bias + activation, write g_gates fp16
#pragma unroll
    for (int mt = 0; mt < 4; mt++) {
#pragma unroll
        for (int nt = 0; nt < 4; nt++) {
            int r   = m0 + warp_m * 64 + mt * 16 + (lane >> 2);
            int cgl = n0 + warp_n * 32 + nt * 8 + ((lane & 3) << 1);
            bool isz = (cgl < 256);
            float b0 = __ldg(bias + cgl);
            float b1 = __ldg(bias + cgl + 1);
            float v0 = acc[mt][nt][0] + b0;
            float v1 = acc[mt][nt][1] + b1;
            float v2 = acc[mt][nt][2] + b0;
            float v3 = acc[mt][nt][3] + b1;
            if (isz) {
                v0 = tanh_fast(v0); v1 = tanh_fast(v1);
                v2 = tanh_fast(v2); v3 = tanh_fast(v3);
            } else {
                v0 = sigm(v0); v1 = sigm(v1);
                v2 = sigm(v2); v3 = sigm(v3);
            }
            *(__half2*)&g_gates[(long)r * N_ + cgl]       = __floats2half2_rn(v0, v1);
            *(__half2*)&g_gates[(long)(r + 8) * N_ + cgl] = __floats2half2_rn(v2, v3);
        }
    }
}

// ---------------------------------------------------------------------------
// Fused single-pass scan with decoupled look-back (CUB-style).
// Grid 2048 blocks (bid = b*64 + q), 128 threads, 2 h-chains per thread.
// Pass 1: read z,f (kept in regs), compute local transform (A = prod f, B).
// Publish local; look back over predecessors composing locals (short-circuit
// on inclusive); publish inclusive; Pass 2: read o, replay, write outputs.
// Gates are read exactly once. Predecessors have lower blockIdx -> safe.
// ---------------------------------------------------------------------------
__global__ __launch_bounds__(128)
void scan_fused(const int* __restrict__ mask, float* __restrict__ out)
{
    const int bid = blockIdx.x;
    const int b   = bid >> 6;
    const int q   = bid & 63;
    const int h2  = threadIdx.x;
    const int ci  = bid * H_ + 2 * h2;            // this block's chain slot
    const __half2* gp = (const __half2*)(g_gates + (long)(b * S_ + q * CHLEN) * N_) + h2;

    // ---- Pass 1: z,f -> registers; local transform ----
    __half2 zr[CHLEN], fr[CHLEN];
#pragma unroll
    for (int t = 0; t < CHLEN; t++) {
        const __half2* p = gp + (long)t * (N_ / 2);
        zr[t] = __ldg(p);
        fr[t] = __ldg(p + 128);
    }
    float ax = 1.0f, ay = 1.0f, bx = 0.0f, by = 0.0f;
#pragma unroll
    for (int t = 0; t < CHLEN; t++) {
        float2 z = __half22float2(zr[t]);
        float2 f = __half22float2(fr[t]);
        bx = fmaf(f.x, bx - z.x, z.x);
        by = fmaf(f.y, by - z.y, z.y);
        ax *= f.x; ay *= f.y;
    }

    // ---- Publish local (A, B), flag = 1 ----
    *(float2*)&g_locA[ci] = make_float2(ax, ay);
    *(float2*)&g_locB[ci] = make_float2(bx, by);
    __threadfence();
    __syncthreads();
    if (h2 == 0) *((volatile int*)&g_flag[bid]) = 1;

    // ---- Look-back: exclusive prefix c0 ----
    float c0x = 0.0f, c0y = 0.0f;
    if (q != 0) {
        float uAx = 1.0f, uAy = 1.0f, uBx = 0.0f, uBy = 0.0f;
        const int jmin = b << 6;
        int j = bid - 1;
        for (;;) {
            int s;
            do { s = *((volatile int*)&g_flag[j]); } while (s == 0);
            __threadfence();
            const int jc = j * H_ + 2 * h2;
            if (s == 2) {
                float2 inc = __ldcg((const float2*)&g_incl[jc]);
                c0x = fmaf(uAx, inc.x, uBx);
                c0y = fmaf(uAy, inc.y, uBy);
                break;
            }
            float2 la = __ldcg((const float2*)&g_locA[jc]);
            float2 lb = __ldcg((const float2*)&g_locB[jc]);
            uBx = fmaf(uAx, lb.x, uBx);
            uBy = fmaf(uAy, lb.y, uBy);
            uAx *= la.x; uAy *= la.y;
            if (j == jmin) { c0x = uBx; c0y = uBy; break; }
            j--;
        }
    }

    // ---- Publish inclusive, flag = 2 ----
    *(float2*)&g_incl[ci] = make_float2(fmaf(ax, c0x, bx), fmaf(ay, c0y, by));
    __threadfence();
    __syncthreads();
    if (h2 == 0) *((volatile int*)&g_flag[bid]) = 2;

    // ---- Pass 2: replay with c0, read o, write outputs ----
    int idx = mask[b] - 1;
    if (idx < 0) idx = 0;
    if (idx > S_ - 1) idx = S_ - 1;

    const int chain = b * H_ + 2 * h2;
    float* outT    = out + (long)(b * S_ + q * CHLEN) * H_ + 2 * h2;
    float* outHid  = out + (long)B_ * S_ * H_;
    float* outCell = outHid + B_ * H_;

    float cx = c0x, cy = c0y;
#pragma unroll
    for (int t = 0; t < CHLEN; t++) {
        float2 o = __half22float2(__ldg(gp + (long)t * (N_ / 2) + 256));
        float2 z = __half22float2(zr[t]);
        float2 f = __half22float2(fr[t]);
        cx = fmaf(f.x, cx - z.x, z.x);
        cy = fmaf(f.y, cy - z.y, z.y);
        float2 hv = make_float2(o.x * cx, o.y * cy);
        *(float2*)(outT + (long)t * H_) = hv;
        if (q * CHLEN + t == idx) {
            *(float2*)&outHid[chain]  = hv;
            *(float2*)&outCell[chain] = make_float2(cx, cy);
        }
    }
}

extern "C" void kernel_launch(void* const* d_in, const int* in_sizes, int n_in,
                              void* d_out, int out_size)
{
    const float* x    = (const float*)d_in[0];
    const int*   mask = (const int*)d_in[1];
    const float* W    = (const float*)d_in[2];
    const float* bias = (const float*)d_in[3];
    float* out = (float*)d_out;

    cudaFuncSetAttribute(gates_gemm, cudaFuncAttributeMaxDynamicSharedMemorySize, SMEM_BYTES);

    flag_init<<<NBLK / 256, 256>>>();
    convert_x<<<M_ * E_ / 8 / 256, 256>>>(x);
    prep_w<<<dim3(24, 16), dim3(32, 8)>>>(W);
    gates_gemm<<<dim3(6, 512), 256, SMEM_BYTES>>>(bias);
    scan_fused<<<NBLK, 128>>>(mask, out);
}

// round 12
// speedup vs baseline: 1.2077x; 1.2077x over previous
#include <cuda_runtime.h>
#include <cuda_fp16.h>
#include <cstdint>

// Problem dims
#define B_  32
#define S_  2048
#define E_  256
#define H_  256
#define M_  (B_ * S_)   // 65536
#define N_  (3 * H_)    // 768
#define K_  (2 * E_)    // 512

#define CHUNKS 32
#define CHLEN  (S_ / CHUNKS)   // 64
#define CHAINS (B_ * H_)       // 8192

// Scratch (static device arrays; no allocation)
__device__ __half g_gates[(size_t)M_ * N_];   // activated z|f|o  [M,768] fp16
__device__ __half g_x16[(size_t)M_ * E_];     // x in fp16
__device__ __half g_Wt16[(size_t)N_ * K_];    // W transposed fp16 [768,512]
__device__ float  g_Ac[CHUNKS * CHAINS];
__device__ float  g_Bc[CHUNKS * CHAINS];
__device__ float  g_c0[CHUNKS * CHAINS];

__device__ __forceinline__ float sigm(float x)      { return 1.0f / (1.0f + __expf(-x)); }
__device__ __forceinline__ float tanh_fast(float x) { return 2.0f / (1.0f + __expf(-2.0f * x)) - 1.0f; }

__device__ __forceinline__ uint32_t smem_u32(const void* p) {
    uint32_t a;
    asm("{ .reg .u64 t; cvta.to.shared.u64 t, %1; cvt.u32.u64 %0, t; }" : "=r"(a) : "l"(p));
    return a;
}

#define LDSM_X4(r0, r1, r2, r3, a)                                              \
    asm volatile("ldmatrix.sync.aligned.m8n8.x4.shared.b16 {%0,%1,%2,%3}, [%4];"\
                 : "=r"(r0), "=r"(r1), "=r"(r2), "=r"(r3) : "r"(a))

#define MMA_F16(c, a0, a1, a2, a3, b0, b1)                                      \
    asm volatile("mma.sync.aligned.m16n8k16.row.col.f32.f16.f16.f32 "           \
                 "{%0,%1,%2,%3}, {%4,%5,%6,%7}, {%8,%9}, {%0,%1,%2,%3};"        \
                 : "+f"((c)[0]), "+f"((c)[1]), "+f"((c)[2]), "+f"((c)[3])       \
                 : "r"(a0), "r"(a1), "r"(a2), "r"(a3), "r"(b0), "r"(b1))

__device__ __forceinline__ void cp16(uint32_t dst, const void* src, int sz) {
    asm volatile("cp.async.cg.shared.global [%0], [%1], 16, %2;" :: "r"(dst), "l"(src), "r"(sz));
}
#define CP_COMMIT() asm volatile("cp.async.commit_group;" ::: "memory")
#define CP_WAIT1()  asm volatile("cp.async.wait_group 1;" ::: "memory")

// ---------------------------------------------------------------------------
// x fp32 -> fp16
// ---------------------------------------------------------------------------
__global__ __launch_bounds__(256)
void convert_x(const float* __restrict__ x)
{
    long i = (long)blockIdx.x * 256 + threadIdx.x;     // one float4 pair each
    const float4* src = (const float4*)x;
    float4 v0 = src[2 * i], v1 = src[2 * i + 1];
    __half2 h0 = __floats2half2_rn(v0.x, v0.y);
    __half2 h1 = __floats2half2_rn(v0.z, v0.w);
    __half2 h2 = __floats2half2_rn(v1.x, v1.y);
    __half2 h3 = __floats2half2_rn(v1.z, v1.w);
    uint4 o;
    o.x = *(uint32_t*)&h0; o.y = *(uint32_t*)&h1;
    o.z = *(uint32_t*)&h2; o.w = *(uint32_t*)&h3;
    *((uint4*)g_x16 + i) = o;
}

// ---------------------------------------------------------------------------
// W [512,768] fp32 -> Wt16 [768,512] fp16 (transposed)
// ---------------------------------------------------------------------------
__global__ void prep_w(const float* __restrict__ W)
{
    __shared__ float t[32][33];
    int n = blockIdx.x * 32 + threadIdx.x;
    int k = blockIdx.y * 32 + threadIdx.y;
#pragma unroll
    for (int j = 0; j < 32; j += 8)
        t[threadIdx.y + j][threadIdx.x] = W[(long)(k + j) * N_ + n];
    __syncthreads();
    int n2 = blockIdx.x * 32 + threadIdx.y;
    int k2 = blockIdx.y * 32 + threadIdx.x;
#pragma unroll
    for (int j = 0; j < 32; j += 8)
        g_Wt16[(long)(n2 + j) * K_ + k2] = __float2half_rn(t[threadIdx.x][threadIdx.y + j]);
}

// ---------------------------------------------------------------------------
// GEMM: gates = [x_t, x_{t-1}] @ W + b, fp16 mma.sync m16n8k16, fp32 accum.
// CTA tile 128x128, BK=64 (8 phases), 8 warps (2x4), warp tile 64x32,
// 3-stage ring / prefetch-distance 2, ONE barrier per phase:
//   wait_group 1 ; sync ; load(q+2 -> stage (q+2)%3) ; commit ; compute(q)
// The sync proves every warp finished compute(q-1), i.e. finished READING
// stage (q+2)%3, so the load can't race readers; no post-compute barrier.
// smem row stride 72 halves (144B): conflict-free ldmatrix.
// B stored [n][k] k-contiguous -> NON-trans ldmatrix = col-major B fragment.
// ---------------------------------------------------------------------------
#define RS        72                      // halves per smem row
#define A_BYTES   (128 * RS * 2)          // 18432
#define STAGE_SZ  (2 * A_BYTES)           // A + B = 36864
#define STAGES    3
#define SMEM_BYTES (STAGES * STAGE_SZ)    // 110592 (2 CTAs = 216 KB <= 228 KB)

__global__ __launch_bounds__(256, 2)
void gates_gemm(const float* __restrict__ bias)
{
    extern __shared__ char smem[];
    const uint32_t sb = smem_u32(smem);
    const int tid  = threadIdx.x;
    const int lane = tid & 31;
    const int wid  = tid >> 5;
    const int warp_m = wid & 1;
    const int warp_n = wid >> 1;
    const int m0 = blockIdx.y * 128;
    const int n0 = blockIdx.x * 128;

    auto stageA = [&](int s) -> uint32_t { return sb + s * STAGE_SZ; };
    auto stageB = [&](int s) -> uint32_t { return sb + s * STAGE_SZ + A_BYTES; };

    float acc[4][4][4];
#pragma unroll
    for (int a = 0; a < 4; a++)
#pragma unroll
        for (int b = 0; b < 4; b++)
#pragma unroll
            for (int c = 0; c < 4; c++) acc[a][b][c] = 0.0f;

    // per-thread load geometry: 1024 chunks of 16B per (A|B) tile, 4 per thread
    auto load_tile = [&](int kt, int s) {
        const int k0 = kt * 64;
        const uint32_t ab = stageA(s), bb = stageB(s);
#pragma unroll
        for (int i = 0; i < 4; i++) {
            int idx = tid + i * 256;
            int r = idx >> 3, ci = idx & 7;          // row 0..127, 16B chunk 0..7
            uint32_t dst = ab + r * (RS * 2) + ci * 16;
            int m = m0 + r;
            const __half* src;
            int sz = 16;
            if (k0 < 256) {
                src = g_x16 + (long)m * E_ + k0 + ci * 8;
            } else if ((m & (S_ - 1)) == 0) {
                src = g_x16; sz = 0;                  // t==0: zero fill
            } else {
                src = g_x16 + (long)(m - 1) * E_ + (k0 - 256) + ci * 8;
            }
            cp16(dst, src, sz);
        }
#pragma unroll
        for (int i = 0; i < 4; i++) {
            int idx = tid + i * 256;
            int r = idx >> 3, ci = idx & 7;
            uint32_t dst = bb + r * (RS * 2) + ci * 16;
            cp16(dst, g_Wt16 + (long)(n0 + r) * K_ + k0 + ci * 8, 16);
        }
    };

    load_tile(0, 0); CP_COMMIT();
    load_tile(1, 1); CP_COMMIT();

    for (int kt = 0; kt < 8; kt++) {
        const int s = kt % STAGES;
        CP_WAIT1();          // stage s's copies complete (this thread)
        __syncthreads();     // all threads: stage s visible; compute(kt-1) done

        if (kt + 2 < 8) load_tile(kt + 2, (kt + 2) % STAGES);
        CP_COMMIT();         // possibly-empty group keeps wait_group math

        const uint32_t ab = stageA(s), bb = stageB(s);
#pragma unroll
        for (int ks = 0; ks < 4; ks++) {
            const int kk = ks * 16;
            uint32_t af[4][4], bf[4][2];
#pragma unroll
            for (int mt = 0; mt < 4; mt++) {
                int mBase = warp_m * 64 + mt * 16;
                int mi = lane >> 3;
                int row = mBase + ((mi & 1) << 3) + (lane & 7);
                int col = kk + ((mi >> 1) << 3);
                uint32_t a = ab + (row * RS + col) * 2;
                LDSM_X4(af[mt][0], af[mt][1], af[mt][2], af[mt][3], a);
            }
#pragma unroll
            for (int p = 0; p < 2; p++) {
                int nBase = warp_n * 32 + p * 16;
                int mi = lane >> 3;
                int row = nBase + ((mi >> 1) << 3) + (lane & 7);
                int col = kk + ((mi & 1) << 3);
                uint32_t a = bb + (row * RS + col) * 2;
                LDSM_X4(bf[2 * p][0], bf[2 * p][1], bf[2 * p + 1][0], bf[2 * p + 1][1], a);
            }
#pragma unroll
            for (int mt = 0; mt < 4; mt++)
#pragma unroll
                for (int nt = 0; nt < 4; nt++)
                    MMA_F16(acc[mt][nt], af[mt][0], af[mt][1], af[mt][2], af[mt][3],
                            bf[nt][0], bf[nt][1]);
        }
    }

    // Epilogue: bias + activation, write g_gates fp16
#pragma unroll
    for (int mt = 0; mt < 4; mt++) {
#pragma unroll
        for (int nt = 0; nt < 4; nt++) {
            int r   = m0 + warp_m * 64 + mt * 16 + (lane >> 2);
            int cgl = n0 + warp_n * 32 + nt * 8 + ((lane & 3) << 1);
            bool isz = (cgl < 256);
            float b0 = __ldg(bias + cgl);
            float b1 = __ldg(bias + cgl + 1);
            float v0 = acc[mt][nt][0] + b0;
            float v1 = acc[mt][nt][1] + b1;
            float v2 = acc[mt][nt][2] + b0;
            float v3 = acc[mt][nt][3] + b1;
            if (isz) {
                v0 = tanh_fast(v0); v1 = tanh_fast(v1);
                v2 = tanh_fast(v2); v3 = tanh_fast(v3);
            } else {
                v0 = sigm(v0); v1 = sigm(v1);
                v2 = sigm(v2); v3 = sigm(v3);
            }
            *(__half2*)&g_gates[(long)r * N_ + cgl]       = __floats2half2_rn(v0, v1);
            *(__half2*)&g_gates[(long)(r + 8) * N_ + cgl] = __floats2half2_rn(v2, v3);
        }
    }
}

// ---------------------------------------------------------------------------
// Scan pass 1: per (chain-pair, chunk): A = prod(f), B = c(chunk | c_in = 0)
// 1024 x 128 thr; 2 h per thread (half2). CHLEN=64.
// ---------------------------------------------------------------------------
__global__ __launch_bounds__(128)
void scan_p1()
{
    const int b = blockIdx.x >> 5, q = blockIdx.x & 31, h2 = threadIdx.x;
    const __half2* gp = (const __half2*)(g_gates + (long)(b * S_ + q * CHLEN) * N_) + h2;

    float ax = 1.0f, ay = 1.0f, cx = 0.0f, cy = 0.0f;
    for (int t0 = 0; t0 < CHLEN; t0 += 8) {
        __half2 z2[8], f2[8];
#pragma unroll
        for (int j = 0; j < 8; j++) {
            const __half2* p = gp + (long)(t0 + j) * (N_ / 2);
            z2[j] = __ldg(p);
            f2[j] = __ldg(p + 128);
        }
#pragma unroll
        for (int j = 0; j < 8; j++) {
            float2 z = __half22float2(z2[j]);
            float2 f = __half22float2(f2[j]);
            cx = fmaf(f.x, cx - z.x, z.x);
            cy = fmaf(f.y, cy - z.y, z.y);
            ax *= f.x; ay *= f.y;
        }
    }
    const int chain = b * H_ + 2 * h2;
    *(float2*)&g_Ac[q * CHAINS + chain] = make_float2(ax, ay);
    *(float2*)&g_Bc[q * CHAINS + chain] = make_float2(cx, cy);
}

// ---------------------------------------------------------------------------
// Scan pass 2: sequential combine over 32 chunks -> chunk-initial c
// ---------------------------------------------------------------------------
__global__ __launch_bounds__(256)
void scan_p2()
{
    const int chain = blockIdx.x * 256 + threadIdx.x;
    float c = 0.0f;
#pragma unroll
    for (int q = 0; q < CHUNKS; q++) {
        g_c0[q * CHAINS + chain] = c;
        c = g_Ac[q * CHAINS + chain] * c + g_Bc[q * CHAINS + chain];
    }
}

// ---------------------------------------------------------------------------
// Scan pass 3: within-chunk scan with correct initial c; write outputs.
// 1024 x 128 thr; half2 gates, float2 stores. CHLEN=64.
// ---------------------------------------------------------------------------
__global__ __launch_bounds__(128)
void scan_p3(const int* __restrict__ mask, float* __restrict__ out)
{
    const int b = blockIdx.x >> 5, q = blockIdx.x & 31, h2 = threadIdx.x;
    const int chain = b * H_ + 2 * h2;
    const __half2* gp = (const __half2*)(g_gates + (long)(b * S_ + q * CHLEN) * N_) + h2;

    int idx = mask[b] - 1;
    if (idx < 0) idx = 0;
    if (idx > S_ - 1) idx = S_ - 1;

    float* outT    = out + (long)(b * S_ + q * CHLEN) * H_ + 2 * h2;
    float* outHid  = out + (long)B_ * S_ * H_;
    float* outCell = outHid + B_ * H_;

    float2 c = *(const float2*)&g_c0[q * CHAINS + chain];
    for (int t0 = 0; t0 < CHLEN; t0 += 8) {
        __half2 z2[8], f2[8], o2[8];
#pragma unroll
        for (int j = 0; j < 8; j++) {
            const __half2* p = gp + (long)(t0 + j) * (N_ / 2);
            z2[j] = __ldg(p);
            f2[j] = __ldg(p + 128);
            o2[j] = __ldg(p + 256);
        }
#pragma unroll
        for (int j = 0; j < 8; j++) {
            float2 z = __half22float2(z2[j]);
            float2 f = __half22float2(f2[j]);
            float2 o = __half22float2(o2[j]);
            c.x = fmaf(f.x, c.x - z.x, z.x);
            c.y = fmaf(f.y, c.y - z.y, z.y);
            float2 hv = make_float2(o.x * c.x, o.y * c.y);
            *(float2*)(outT + (long)(t0 + j) * H_) = hv;
            if (q * CHLEN + t0 + j == idx) {
                *(float2*)&outHid[chain]  = hv;
                *(float2*)&outCell[chain] = c;
            }
        }
    }
}

extern "C" void kernel_launch(void* const* d_in, const int* in_sizes, int n_in,
                              void* d_out, int out_size)
{
    const float* x    = (const float*)d_in[0];
    const int*   mask = (const int*)d_in[1];
    const float* W    = (const float*)d_in[2];
    const float* bias = (const float*)d_in[3];
    float* out = (float*)d_out;

    cudaFuncSetAttribute(gates_gemm, cudaFuncAttributeMaxDynamicSharedMemorySize, SMEM_BYTES);

    convert_x<<<M_ * E_ / 8 / 256, 256>>>(x);
    prep_w<<<dim3(24, 16), dim3(32, 8)>>>(W);
    gates_gemm<<<dim3(6, 512), 256, SMEM_BYTES>>>(bias);
    scan_p1<<<B_ * CHUNKS, 128>>>();
    scan_p2<<<CHAINS / 256, 256>>>();
    scan_p3<<<B_ * CHUNKS, 128>>>(mask, out);
}

// round 13
// speedup vs baseline: 1.2160x; 1.0069x over previous
#include <cuda_runtime.h>
#include <cuda_fp16.h>
#include <cstdint>

// Problem dims
#define B_  32
#define S_  2048
#define E_  256
#define H_  256
#define M_  (B_ * S_)   // 65536
#define N_  (3 * H_)    // 768
#define K_  (2 * E_)    // 512

#define CHUNKS 32
#define CHLEN  (S_ / CHUNKS)   // 64
#define CHAINS (B_ * H_)       // 8192

// Scratch (static device arrays; no allocation)
__device__ __half g_gates[(size_t)M_ * N_];   // activated z|f|o  [M,768] fp16
__device__ __half g_x16[(size_t)M_ * E_];     // x in fp16
__device__ __half g_Wt16[(size_t)N_ * K_];    // W transposed fp16 [768,512]
__device__ float  g_Ac[CHUNKS * CHAINS];
__device__ float  g_Bc[CHUNKS * CHAINS];
__device__ float  g_c0[CHUNKS * CHAINS];

__device__ __forceinline__ float sigm(float x)      { return 1.0f / (1.0f + __expf(-x)); }
__device__ __forceinline__ float tanh_fast(float x) { return 2.0f / (1.0f + __expf(-2.0f * x)) - 1.0f; }

__device__ __forceinline__ uint32_t smem_u32(const void* p) {
    uint32_t a;
    asm("{ .reg .u64 t; cvta.to.shared.u64 t, %1; cvt.u32.u64 %0, t; }" : "=r"(a) : "l"(p));
    return a;
}

#define LDSM_X4(r0, r1, r2, r3, a)                                              \
    asm volatile("ldmatrix.sync.aligned.m8n8.x4.shared.b16 {%0,%1,%2,%3}, [%4];"\
                 : "=r"(r0), "=r"(r1), "=r"(r2), "=r"(r3) : "r"(a))

#define MMA_F16(c, a0, a1, a2, a3, b0, b1)                                      \
    asm volatile("mma.sync.aligned.m16n8k16.row.col.f32.f16.f16.f32 "           \
                 "{%0,%1,%2,%3}, {%4,%5,%6,%7}, {%8,%9}, {%0,%1,%2,%3};"        \
                 : "+f"((c)[0]), "+f"((c)[1]), "+f"((c)[2]), "+f"((c)[3])       \
                 : "r"(a0), "r"(a1), "r"(a2), "r"(a3), "r"(b0), "r"(b1))

__device__ __forceinline__ void cp16(uint32_t dst, const void* src, int sz) {
    asm volatile("cp.async.cg.shared.global [%0], [%1], 16, %2;" :: "r"(dst), "l"(src), "r"(sz));
}
#define CP_COMMIT() asm volatile("cp.async.commit_group;" ::: "memory")
#define CP_WAIT1()  asm volatile("cp.async.wait_group 1;" ::: "memory")

// ---------------------------------------------------------------------------
// Fused prep: blocks [0, 8192) convert x fp32->fp16 (32B/thread);
// blocks [8192, 8576) transpose+convert W -> Wt16 [768,512].
// Independent outputs; merging removes one launch boundary and lets the small
// transpose ride inside the big convert's wave instead of serializing.
// ---------------------------------------------------------------------------
#define XBLK (M_ * E_ / 8 / 256)   // 8192
#define WBLK (24 * 16)             // 384

__global__ __launch_bounds__(256)
void prep_fused(const float* __restrict__ x, const float* __restrict__ W)
{
    if (blockIdx.x < XBLK) {
        long i = (long)blockIdx.x * 256 + threadIdx.x;   // one float4 pair each
        const float4* src = (const float4*)x;
        float4 v0 = src[2 * i], v1 = src[2 * i + 1];
        __half2 h0 = __floats2half2_rn(v0.x, v0.y);
        __half2 h1 = __floats2half2_rn(v0.z, v0.w);
        __half2 h2 = __floats2half2_rn(v1.x, v1.y);
        __half2 h3 = __floats2half2_rn(v1.z, v1.w);
        uint4 o;
        o.x = *(uint32_t*)&h0; o.y = *(uint32_t*)&h1;
        o.z = *(uint32_t*)&h2; o.w = *(uint32_t*)&h3;
        *((uint4*)g_x16 + i) = o;
    } else {
        __shared__ float t[32][33];
        int wb = blockIdx.x - XBLK;          // 0..383 = (24 n-blocks) x (16 k-blocks)
        int bxn = wb % 24, byk = wb / 24;
        int tx = threadIdx.x & 31, ty = threadIdx.x >> 5;   // 32 x 8
        int n = bxn * 32 + tx;
        int k = byk * 32 + ty;
#pragma unroll
        for (int j = 0; j < 32; j += 8)
            t[ty + j][tx] = W[(long)(k + j) * N_ + n];
        __syncthreads();
        int n2 = bxn * 32 + ty;
        int k2 = byk * 32 + tx;
#pragma unroll
        for (int j = 0; j < 32; j += 8)
            g_Wt16[(long)(n2 + j) * K_ + k2] = __float2half_rn(t[tx][ty + j]);
    }
}

// ---------------------------------------------------------------------------
// GEMM (best measured): gates = [x_t, x_{t-1}] @ W + b.
// fp16 mma.sync m16n8k16, fp32 accum. CTA tile 128x128, BK=64 (8 phases),
// 8 warps (2x4), warp tile 64x32, 3-stage ring / prefetch distance 2,
// single barrier per phase, 256 thr, 2 CTAs/SM (16 warps/SM).
// smem row stride 72 halves (144B): conflict-free ldmatrix.
// B stored [n][k] k-contiguous -> NON-trans ldmatrix = col-major B fragment.
// ---------------------------------------------------------------------------
#define RS        72                      // halves per smem row
#define A_BYTES   (128 * RS * 2)          // 18432
#define STAGE_SZ  (2 * A_BYTES)           // A + B = 36864
#define STAGES    3
#define SMEM_BYTES (STAGES * STAGE_SZ)    // 110592 (2 CTAs = 216 KB <= 228 KB)

__global__ __launch_bounds__(256, 2)
void gates_gemm(const float* __restrict__ bias)
{
    extern __shared__ char smem[];
    const uint32_t sb = smem_u32(smem);
    const int tid  = threadIdx.x;
    const int lane = tid & 31;
    const int wid  = tid >> 5;
    const int warp_m = wid & 1;
    const int warp_n = wid >> 1;
    const int m0 = blockIdx.y * 128;
    const int n0 = blockIdx.x * 128;

    auto stageA = [&](int s) -> uint32_t { return sb + s * STAGE_SZ; };
    auto stageB = [&](int s) -> uint32_t { return sb + s * STAGE_SZ + A_BYTES; };

    float acc[4][4][4];
#pragma unroll
    for (int a = 0; a < 4; a++)
#pragma unroll
        for (int b = 0; b < 4; b++)
#pragma unroll
            for (int c = 0; c < 4; c++) acc[a][b][c] = 0.0f;

    auto load_tile = [&](int kt, int s) {
        const int k0 = kt * 64;
        const uint32_t ab = stageA(s), bb = stageB(s);
#pragma unroll
        for (int i = 0; i < 4; i++) {
            int idx = tid + i * 256;
            int r = idx >> 3, ci = idx & 7;          // row 0..127, 16B chunk 0..7
            uint32_t dst = ab + r * (RS * 2) + ci * 16;
            int m = m0 + r;
            const __half* src;
            int sz = 16;
            if (k0 < 256) {
                src = g_x16 + (long)m * E_ + k0 + ci * 8;
            } else if ((m & (S_ - 1)) == 0) {
                src = g_x16; sz = 0;                  // t==0: zero fill
            } else {
                src = g_x16 + (long)(m - 1) * E_ + (k0 - 256) + ci * 8;
            }
            cp16(dst, src, sz);
        }
#pragma unroll
        for (int i = 0; i < 4; i++) {
            int idx = tid + i * 256;
            int r = idx >> 3, ci = idx & 7;
            uint32_t dst = bb + r * (RS * 2) + ci * 16;
            cp16(dst, g_Wt16 + (long)(n0 + r) * K_ + k0 + ci * 8, 16);
        }
    };

    load_tile(0, 0); CP_COMMIT();
    load_tile(1, 1); CP_COMMIT();

    for (int kt = 0; kt < 8; kt++) {
        const int s = kt % STAGES;
        CP_WAIT1();          // stage s's copies complete (this thread)
        __syncthreads();     // all threads: stage s visible; compute(kt-1) done

        if (kt + 2 < 8) load_tile(kt + 2, (kt + 2) % STAGES);
        CP_COMMIT();         // possibly-empty group keeps wait_group math

        const uint32_t ab = stageA(s), bb = stageB(s);
#pragma unroll
        for (int ks = 0; ks < 4; ks++) {
            const int kk = ks * 16;
            uint32_t af[4][4], bf[4][2];
#pragma unroll
            for (int mt = 0; mt < 4; mt++) {
                int mBase = warp_m * 64 + mt * 16;
                int mi = lane >> 3;
                int row = mBase + ((mi & 1) << 3) + (lane & 7);
                int col = kk + ((mi >> 1) << 3);
                uint32_t a = ab + (row * RS + col) * 2;
                LDSM_X4(af[mt][0], af[mt][1], af[mt][2], af[mt][3], a);
            }
#pragma unroll
            for (int p = 0; p < 2; p++) {
                int nBase = warp_n * 32 + p * 16;
                int mi = lane >> 3;
                int row = nBase + ((mi >> 1) << 3) + (lane & 7);
                int col = kk + ((mi & 1) << 3);
                uint32_t a = bb + (row * RS + col) * 2;
                LDSM_X4(bf[2 * p][0], bf[2 * p][1], bf[2 * p + 1][0], bf[2 * p + 1][1], a);
            }
#pragma unroll
            for (int mt = 0; mt < 4; mt++)
#pragma unroll
                for (int nt = 0; nt < 4; nt++)
                    MMA_F16(acc[mt][nt], af[mt][0], af[mt][1], af[mt][2], af[mt][3],
                            bf[nt][0], bf[nt][1]);
        }
    }

    // Epilogue: bias + activation, write g_gates fp16
#pragma unroll
    for (int mt = 0; mt < 4; mt++) {
#pragma unroll
        for (int nt = 0; nt < 4; nt++) {
            int r   = m0 + warp_m * 64 + mt * 16 + (lane >> 2);
            int cgl = n0 + warp_n * 32 + nt * 8 + ((lane & 3) << 1);
            bool isz = (cgl < 256);
            float b0 = __ldg(bias + cgl);
            float b1 = __ldg(bias + cgl + 1);
            float v0 = acc[mt][nt][0] + b0;
            float v1 = acc[mt][nt][1] + b1;
            float v2 = acc[mt][nt][2] + b0;
            float v3 = acc[mt][nt][3] + b1;
            if (isz) {
                v0 = tanh_fast(v0); v1 = tanh_fast(v1);
                v2 = tanh_fast(v2); v3 = tanh_fast(v3);
            } else {
                v0 = sigm(v0); v1 = sigm(v1);
                v2 = sigm(v2); v3 = sigm(v3);
            }
            *(__half2*)&g_gates[(long)r * N_ + cgl]       = __floats2half2_rn(v0, v1);
            *(__half2*)&g_gates[(long)(r + 8) * N_ + cgl] = __floats2half2_rn(v2, v3);
        }
    }
}

// ---------------------------------------------------------------------------
// Scan pass 1: per (chain-pair, chunk): A = prod(f), B = c(chunk | c_in = 0)
// 1024 x 128 thr; 2 h per thread (half2). CHLEN=64.
// ---------------------------------------------------------------------------
__global__ __launch_bounds__(128)
void scan_p1()
{
    const int b = blockIdx.x >> 5, q = blockIdx.x & 31, h2 = threadIdx.x;
    const __half2* gp = (const __half2*)(g_gates + (long)(b * S_ + q * CHLEN) * N_) + h2;

    float ax = 1.0f, ay = 1.0f, cx = 0.0f, cy = 0.0f;
    for (int t0 = 0; t0 < CHLEN; t0 += 8) {
        __half2 z2[8], f2[8];
#pragma unroll
        for (int j = 0; j < 8; j++) {
            const __half2* p = gp + (long)(t0 + j) * (N_ / 2);
            z2[j] = __ldg(p);
            f2[j] = __ldg(p + 128);
        }
#pragma unroll
        for (int j = 0; j < 8; j++) {
            float2 z = __half22float2(z2[j]);
            float2 f = __half22float2(f2[j]);
            cx = fmaf(f.x, cx - z.x, z.x);
            cy = fmaf(f.y, cy - z.y, z.y);
            ax *= f.x; ay *= f.y;
        }
    }
    const int chain = b * H_ + 2 * h2;
    *(float2*)&g_Ac[q * CHAINS + chain] = make_float2(ax, ay);
    *(float2*)&g_Bc[q * CHAINS + chain] = make_float2(cx, cy);
}

// ---------------------------------------------------------------------------
// Scan pass 2: sequential combine over 32 chunks -> chunk-initial c
// ---------------------------------------------------------------------------
__global__ __launch_bounds__(256)
void scan_p2()
{
    const int chain = blockIdx.x * 256 + threadIdx.x;
    float c = 0.0f;
#pragma unroll
    for (int q = 0; q < CHUNKS; q++) {
        g_c0[q * CHAINS + chain] = c;
        c = g_Ac[q * CHAINS + chain] * c + g_Bc[q * CHAINS + chain];
    }
}

// ---------------------------------------------------------------------------
// Scan pass 3: within-chunk scan with correct initial c; write outputs.
// 1024 x 128 thr; half2 gates, float2 stores. CHLEN=64.
// ---------------------------------------------------------------------------
__global__ __launch_bounds__(128)
void scan_p3(const int* __restrict__ mask, float* __restrict__ out)
{
    const int b = blockIdx.x >> 5, q = blockIdx.x & 31, h2 = threadIdx.x;
    const int chain = b * H_ + 2 * h2;
    const __half2* gp = (const __half2*)(g_gates + (long)(b * S_ + q * CHLEN) * N_) + h2;

    int idx = mask[b] - 1;
    if (idx < 0) idx = 0;
    if (idx > S_ - 1) idx = S_ - 1;

    float* outT    = out + (long)(b * S_ + q * CHLEN) * H_ + 2 * h2;
    float* outHid  = out + (long)B_ * S_ * H_;
    float* outCell = outHid + B_ * H_;

    float2 c = *(const float2*)&g_c0[q * CHAINS + chain];
    for (int t0 = 0; t0 < CHLEN; t0 += 8) {
        __half2 z2[8], f2[8], o2[8];
#pragma unroll
        for (int j = 0; j < 8; j++) {
            const __half2* p = gp + (long)(t0 + j) * (N_ / 2);
            z2[j] = __ldg(p);
            f2[j] = __ldg(p + 128);
            o2[j] = __ldg(p + 256);
        }
#pragma unroll
        for (int j = 0; j < 8; j++) {
            float2 z = __half22float2(z2[j]);
            float2 f = __half22float2(f2[j]);
            float2 o = __half22float2(o2[j]);
            c.x = fmaf(f.x, c.x - z.x, z.x);
            c.y = fmaf(f.y, c.y - z.y, z.y);
            float2 hv = make_float2(o.x * c.x, o.y * c.y);
            *(float2*)(outT + (long)(t0 + j) * H_) = hv;
            if (q * CHLEN + t0 + j == idx) {
                *(float2*)&outHid[chain]  = hv;
                *(float2*)&outCell[chain] = c;
            }
        }
    }
}

extern "C" void kernel_launch(void* const* d_in, const int* in_sizes, int n_in,
                              void* d_out, int out_size)
{
    const float* x    = (const float*)d_in[0];
    const int*   mask = (const int*)d_in[1];
    const float* W    = (const float*)d_in[2];
    const float* bias = (const float*)d_in[3];
    float* out = (float*)d_out;

    cudaFuncSetAttribute(gates_gemm, cudaFuncAttributeMaxDynamicSharedMemorySize, SMEM_BYTES);

    prep_fused<<<XBLK + WBLK, 256>>>(x, W);
    gates_gemm<<<dim3(6, 512), 256, SMEM_BYTES>>>(bias);
    scan_p1<<<B_ * CHUNKS, 128>>>();
    scan_p2<<<CHAINS / 256, 256>>>();
    scan_p3<<<B_ * CHUNKS, 128>>>(mask, out);
}

// round 14
// speedup vs baseline: 1.2525x; 1.0299x over previous
#include <cuda_runtime.h>
#include <cuda_fp16.h>
#include <cstdint>

// Problem dims
#define B_  32
#define S_  2048
#define E_  256
#define H_  256
#define M_  (B_ * S_)   // 65536
#define N_  (3 * H_)    // 768
#define K_  (2 * E_)    // 512

#define CHUNKS 32
#define CHLEN  (S_ / CHUNKS)   // 64
#define CHAINS (B_ * H_)       // 8192

// Scratch (static device arrays; no allocation)
__device__ __half g_gates[(size_t)M_ * N_];   // activated z|f|o  [M,768] fp16
__device__ __half g_x16[(size_t)M_ * E_];     // x in fp16
__device__ __half g_Wt16[(size_t)N_ * K_];    // W transposed fp16 [768,512]
__device__ float  g_Ac[CHUNKS * CHAINS];
__device__ float  g_Bc[CHUNKS * CHAINS];
__device__ float  g_c0[CHUNKS * CHAINS];

__device__ __forceinline__ float sigm(float x)      { return 1.0f / (1.0f + __expf(-x)); }
__device__ __forceinline__ float tanh_fast(float x) { return 2.0f / (1.0f + __expf(-2.0f * x)) - 1.0f; }

__device__ __forceinline__ uint32_t smem_u32(const void* p) {
    uint32_t a;
    asm("{ .reg .u64 t; cvta.to.shared.u64 t, %1; cvt.u32.u64 %0, t; }" : "=r"(a) : "l"(p));
    return a;
}

#define LDSM_X4(r0, r1, r2, r3, a)                                              \
    asm volatile("ldmatrix.sync.aligned.m8n8.x4.shared.b16 {%0,%1,%2,%3}, [%4];"\
                 : "=r"(r0), "=r"(r1), "=r"(r2), "=r"(r3) : "r"(a))

#define MMA_F16(c, a0, a1, a2, a3, b0, b1)                                      \
    asm volatile("mma.sync.aligned.m16n8k16.row.col.f32.f16.f16.f32 "           \
                 "{%0,%1,%2,%3}, {%4,%5,%6,%7}, {%8,%9}, {%0,%1,%2,%3};"        \
                 : "+f"((c)[0]), "+f"((c)[1]), "+f"((c)[2]), "+f"((c)[3])       \
                 : "r"(a0), "r"(a1), "r"(a2), "r"(a3), "r"(b0), "r"(b1))

__device__ __forceinline__ void cp16(uint32_t dst, const void* src, int sz) {
    asm volatile("cp.async.cg.shared.global [%0], [%1], 16, %2;" :: "r"(dst), "l"(src), "r"(sz));
}
#define CP_COMMIT() asm volatile("cp.async.commit_group;" ::: "memory")
#define CP_WAIT1()  asm volatile("cp.async.wait_group 1;" ::: "memory")

// ---------------------------------------------------------------------------
// Fused prep: blocks [0, 8192) convert x fp32->fp16 (32B/thread);
// blocks [8192, 8576) transpose+convert W -> Wt16 [768,512].
// ---------------------------------------------------------------------------
#define XBLK (M_ * E_ / 8 / 256)   // 8192
#define WBLK (24 * 16)             // 384

__global__ __launch_bounds__(256)
void prep_fused(const float* __restrict__ x, const float* __restrict__ W)
{
    if (blockIdx.x < XBLK) {
        long i = (long)blockIdx.x * 256 + threadIdx.x;   // one float4 pair each
        const float4* src = (const float4*)x;
        float4 v0 = src[2 * i], v1 = src[2 * i + 1];
        __half2 h0 = __floats2half2_rn(v0.x, v0.y);
        __half2 h1 = __floats2half2_rn(v0.z, v0.w);
        __half2 h2 = __floats2half2_rn(v1.x, v1.y);
        __half2 h3 = __floats2half2_rn(v1.z, v1.w);
        uint4 o;
        o.x = *(uint32_t*)&h0; o.y = *(uint32_t*)&h1;
        o.z = *(uint32_t*)&h2; o.w = *(uint32_t*)&h3;
        *((uint4*)g_x16 + i) = o;
    } else {
        __shared__ float t[32][33];
        int wb = blockIdx.x - XBLK;          // 0..383 = (24 n-blocks) x (16 k-blocks)
        int bxn = wb % 24, byk = wb / 24;
        int tx = threadIdx.x & 31, ty = threadIdx.x >> 5;   // 32 x 8
        int n = bxn * 32 + tx;
        int k = byk * 32 + ty;
#pragma unroll
        for (int j = 0; j < 32; j += 8)
            t[ty + j][tx] = W[(long)(k + j) * N_ + n];
        __syncthreads();
        int n2 = bxn * 32 + ty;
        int k2 = byk * 32 + tx;
#pragma unroll
        for (int j = 0; j < 32; j += 8)
            g_Wt16[(long)(n2 + j) * K_ + k2] = __float2half_rn(t[tx][ty + j]);
    }
}

// ---------------------------------------------------------------------------
// GEMM (best measured): gates = [x_t, x_{t-1}] @ W + b.
// fp16 mma.sync m16n8k16, fp32 accum. CTA tile 128x128, BK=64 (8 phases),
// 8 warps (2x4), warp tile 64x32, 3-stage ring / prefetch distance 2,
// single barrier per phase, 256 thr, 2 CTAs/SM (16 warps/SM).
// smem row stride 72 halves (144B): conflict-free ldmatrix.
// B stored [n][k] k-contiguous -> NON-trans ldmatrix = col-major B fragment.
// ---------------------------------------------------------------------------
#define RS        72                      // halves per smem row
#define A_BYTES   (128 * RS * 2)          // 18432
#define STAGE_SZ  (2 * A_BYTES)           // A + B = 36864
#define STAGES    3
#define SMEM_BYTES (STAGES * STAGE_SZ)    // 110592 (2 CTAs = 216 KB <= 228 KB)

__global__ __launch_bounds__(256, 2)
void gates_gemm(const float* __restrict__ bias)
{
    extern __shared__ char smem[];
    const uint32_t sb = smem_u32(smem);
    const int tid  = threadIdx.x;
    const int lane = tid & 31;
    const int wid  = tid >> 5;
    const int warp_m = wid & 1;
    const int warp_n = wid >> 1;
    const int m0 = blockIdx.y * 128;
    const int n0 = blockIdx.x * 128;

    auto stageA = [&](int s) -> uint32_t { return sb + s * STAGE_SZ; };
    auto stageB = [&](int s) -> uint32_t { return sb + s * STAGE_SZ + A_BYTES; };

    float acc[4][4][4];
#pragma unroll
    for (int a = 0; a < 4; a++)
#pragma unroll
        for (int b = 0; b < 4; b++)
#pragma unroll
            for (int c = 0; c < 4; c++) acc[a][b][c] = 0.0f;

    auto load_tile = [&](int kt, int s) {
        const int k0 = kt * 64;
        const uint32_t ab = stageA(s), bb = stageB(s);
#pragma unroll
        for (int i = 0; i < 4; i++) {
            int idx = tid + i * 256;
            int r = idx >> 3, ci = idx & 7;          // row 0..127, 16B chunk 0..7
            uint32_t dst = ab + r * (RS * 2) + ci * 16;
            int m = m0 + r;
            const __half* src;
            int sz = 16;
            if (k0 < 256) {
                src = g_x16 + (long)m * E_ + k0 + ci * 8;
            } else if ((m & (S_ - 1)) == 0) {
                src = g_x16; sz = 0;                  // t==0: zero fill
            } else {
                src = g_x16 + (long)(m - 1) * E_ + (k0 - 256) + ci * 8;
            }
            cp16(dst, src, sz);
        }
#pragma unroll
        for (int i = 0; i < 4; i++) {
            int idx = tid + i * 256;
            int r = idx >> 3, ci = idx & 7;
            uint32_t dst = bb + r * (RS * 2) + ci * 16;
            cp16(dst, g_Wt16 + (long)(n0 + r) * K_ + k0 + ci * 8, 16);
        }
    };

    load_tile(0, 0); CP_COMMIT();
    load_tile(1, 1); CP_COMMIT();

    for (int kt = 0; kt < 8; kt++) {
        const int s = kt % STAGES;
        CP_WAIT1();          // stage s's copies complete (this thread)
        __syncthreads();     // all threads: stage s visible; compute(kt-1) done

        if (kt + 2 < 8) load_tile(kt + 2, (kt + 2) % STAGES);
        CP_COMMIT();         // possibly-empty group keeps wait_group math

        const uint32_t ab = stageA(s), bb = stageB(s);
#pragma unroll
        for (int ks = 0; ks < 4; ks++) {
            const int kk = ks * 16;
            uint32_t af[4][4], bf[4][2];
#pragma unroll
            for (int mt = 0; mt < 4; mt++) {
                int mBase = warp_m * 64 + mt * 16;
                int mi = lane >> 3;
                int row = mBase + ((mi & 1) << 3) + (lane & 7);
                int col = kk + ((mi >> 1) << 3);
                uint32_t a = ab + (row * RS + col) * 2;
                LDSM_X4(af[mt][0], af[mt][1], af[mt][2], af[mt][3], a);
            }
#pragma unroll
            for (int p = 0; p < 2; p++) {
                int nBase = warp_n * 32 + p * 16;
                int mi = lane >> 3;
                int row = nBase + ((mi >> 1) << 3) + (lane & 7);
                int col = kk + ((mi & 1) << 3);
                uint32_t a = bb + (row * RS + col) * 2;
                LDSM_X4(bf[2 * p][0], bf[2 * p][1], bf[2 * p + 1][0], bf[2 * p + 1][1], a);
            }
#pragma unroll
            for (int mt = 0; mt < 4; mt++)
#pragma unroll
                for (int nt = 0; nt < 4; nt++)
                    MMA_F16(acc[mt][nt], af[mt][0], af[mt][1], af[mt][2], af[mt][3],
                            bf[nt][0], bf[nt][1]);
        }
    }

    // Epilogue: bias + activation, write g_gates fp16
#pragma unroll
    for (int mt = 0; mt < 4; mt++) {
#pragma unroll
        for (int nt = 0; nt < 4; nt++) {
            int r   = m0 + warp_m * 64 + mt * 16 + (lane >> 2);
            int cgl = n0 + warp_n * 32 + nt * 8 + ((lane & 3) << 1);
            bool isz = (cgl < 256);
            float b0 = __ldg(bias + cgl);
            float b1 = __ldg(bias + cgl + 1);
            float v0 = acc[mt][nt][0] + b0;
            float v1 = acc[mt][nt][1] + b1;
            float v2 = acc[mt][nt][2] + b0;
            float v3 = acc[mt][nt][3] + b1;
            if (isz) {
                v0 = tanh_fast(v0); v1 = tanh_fast(v1);
                v2 = tanh_fast(v2); v3 = tanh_fast(v3);
            } else {
                v0 = sigm(v0); v1 = sigm(v1);
                v2 = sigm(v2); v3 = sigm(v3);
            }
            *(__half2*)&g_gates[(long)r * N_ + cgl]       = __floats2half2_rn(v0, v1);
            *(__half2*)&g_gates[(long)(r + 8) * N_ + cgl] = __floats2half2_rn(v2, v3);
        }
    }
}

// ---------------------------------------------------------------------------
// Scan pass 1: per (chain-pair, chunk): A = prod(f), B = c(chunk | c_in = 0)
// 1024 x 128 thr; 2 h per thread (half2). CHLEN=64.
// ---------------------------------------------------------------------------
__global__ __launch_bounds__(128)
void scan_p1()
{
    const int b = blockIdx.x >> 5, q = blockIdx.x & 31, h2 = threadIdx.x;
    const __half2* gp = (const __half2*)(g_gates + (long)(b * S_ + q * CHLEN) * N_) + h2;

    float ax = 1.0f, ay = 1.0f, cx = 0.0f, cy = 0.0f;
    for (int t0 = 0; t0 < CHLEN; t0 += 8) {
        __half2 z2[8], f2[8];
#pragma unroll
        for (int j = 0; j < 8; j++) {
            const __half2* p = gp + (long)(t0 + j) * (N_ / 2);
            z2[j] = __ldg(p);
            f2[j] = __ldg(p + 128);
        }
#pragma unroll
        for (int j = 0; j < 8; j++) {
            float2 z = __half22float2(z2[j]);
            float2 f = __half22float2(f2[j]);
            cx = fmaf(f.x, cx - z.x, z.x);
            cy = fmaf(f.y, cy - z.y, z.y);
            ax *= f.x; ay *= f.y;
        }
    }
    const int chain = b * H_ + 2 * h2;
    *(float2*)&g_Ac[q * CHAINS + chain] = make_float2(ax, ay);
    *(float2*)&g_Bc[q * CHAINS + chain] = make_float2(cx, cy);
}

// ---------------------------------------------------------------------------
// Scan pass 2: sequential combine over 32 chunks -> chunk-initial c.
// 64 x 128 thr. All 64 loads hoisted into register arrays (MLP=64,
// coalesced), then the 32-step FMA chain runs with no memory stalls.
// ---------------------------------------------------------------------------
__global__ __launch_bounds__(128)
void scan_p2()
{
    const int chain = blockIdx.x * 128 + threadIdx.x;
    float Aa[CHUNKS], Bb[CHUNKS];
#pragma unroll
    for (int q = 0; q < CHUNKS; q++) {
        Aa[q] = __ldg(&g_Ac[q * CHAINS + chain]);
        Bb[q] = __ldg(&g_Bc[q * CHAINS + chain]);
    }
    float c = 0.0f;
#pragma unroll
    for (int q = 0; q < CHUNKS; q++) {
        g_c0[q * CHAINS + chain] = c;
        c = fmaf(Aa[q], c, Bb[q]);
    }
}

// ---------------------------------------------------------------------------
// Scan pass 3: within-chunk scan with correct initial c; write outputs.
// 1024 x 128 thr; half2 gates, float2 stores. CHLEN=64.
// ---------------------------------------------------------------------------
__global__ __launch_bounds__(128)
void scan_p3(const int* __restrict__ mask, float* __restrict__ out)
{
    const int b = blockIdx.x >> 5, q = blockIdx.x & 31, h2 = threadIdx.x;
    const int chain = b * H_ + 2 * h2;
    const __half2* gp = (const __half2*)(g_gates + (long)(b * S_ + q * CHLEN) * N_) + h2;

    int idx = mask[b] - 1;
    if (idx < 0) idx = 0;
    if (idx > S_ - 1) idx = S_ - 1;

    float* outT    = out + (long)(b * S_ + q * CHLEN) * H_ + 2 * h2;
    float* outHid  = out + (long)B_ * S_ * H_;
    float* outCell = outHid + B_ * H_;

    float2 c = *(const float2*)&g_c0[q * CHAINS + chain];
    for (int t0 = 0; t0 < CHLEN; t0 += 8) {
        __half2 z2[8], f2[8], o2[8];
#pragma unroll
        for (int j = 0; j < 8; j++) {
            const __half2* p = gp + (long)(t0 + j) * (N_ / 2);
            z2[j] = __ldg(p);
            f2[j] = __ldg(p + 128);
            o2[j] = __ldg(p + 256);
        }
#pragma unroll
        for (int j = 0; j < 8; j++) {
            float2 z = __half22float2(z2[j]);
            float2 f = __half22float2(f2[j]);
            float2 o = __half22float2(o2[j]);
            c.x = fmaf(f.x, c.x - z.x, z.x);
            c.y = fmaf(f.y, c.y - z.y, z.y);
            float2 hv = make_float2(o.x * c.x, o.y * c.y);
            *(float2*)(outT + (long)(t0 + j) * H_) = hv;
            if (q * CHLEN + t0 + j == idx) {
                *(float2*)&outHid[chain]  = hv;
                *(float2*)&outCell[chain] = c;
            }
        }
    }
}

extern "C" void kernel_launch(void* const* d_in, const int* in_sizes, int n_in,
                              void* d_out, int out_size)
{
    const float* x    = (const float*)d_in[0];
    const int*   mask = (const int*)d_in[1];
    const float* W    = (const float*)d_in[2];
    const float* bias = (const float*)d_in[3];
    float* out = (float*)d_out;

    cudaFuncSetAttribute(gates_gemm, cudaFuncAttributeMaxDynamicSharedMemorySize, SMEM_BYTES);

    prep_fused<<<XBLK + WBLK, 256>>>(x, W);
    gates_gemm<<<dim3(6, 512), 256, SMEM_BYTES>>>(bias);
    scan_p1<<<B_ * CHUNKS, 128>>>();
    scan_p2<<<CHAINS / 128, 128>>>();
    scan_p3<<<B_ * CHUNKS, 128>>>(mask, out);
}